// round 10
// baseline (speedup 1.0000x reference)
#include <cuda_runtime.h>

#define Dd 160
#define Hh 192
#define Ww 160
#define HW (Hh * Ww)
#define DHW (Dd * Hh * Ww)
#define NSUB (DHW / 8)
#define NB 2
#define S2_BLOCK 256
#define S2_BLOCKS_PER_B (NSUB / S2_BLOCK)       // 2400
#define S2_TOTAL_BLOCKS (NB * S2_BLOCKS_PER_B)  // 4800

// flow_fwd channel-interleaved: (c0,c1,c2,pad) per voxel.
__device__ float4 g_fwd4[NB * DHW];
// Composed displacement field, channel-interleaved.
__device__ float4 g_comp[NB * DHW];
__device__ float g_partial[S2_TOTAL_BLOCKS];

// ---------------------------------------------------------------------------
// Stage 0: interleave flow_fwd [B,3,D,H,W] -> float4 per voxel.
// 4 voxels per thread: 3x LDG.128 (one per channel plane) + 4x STG.128.
// Pure streaming, DRAM-bound.
// ---------------------------------------------------------------------------
__global__ __launch_bounds__(256) void interleave_kernel(const float* __restrict__ ffwd) {
    const long q = (long)blockIdx.x * 256 + threadIdx.x;  // over (NB*DHW)/4
    const int b = (int)(q / (DHW / 4));
    const long lin4 = q - (long)b * (DHW / 4);            // quad index within batch
    const long bbase = (long)b * 3 * DHW;

    const float4 c0 = __ldg((const float4*)(ffwd + bbase) + lin4);
    const float4 c1 = __ldg((const float4*)(ffwd + bbase + DHW) + lin4);
    const float4 c2 = __ldg((const float4*)(ffwd + bbase + 2 * DHW) + lin4);

    float4* __restrict__ dst = g_fwd4 + (long)b * DHW + lin4 * 4;
    dst[0] = make_float4(c0.x, c1.x, c2.x, 0.0f);
    dst[1] = make_float4(c0.y, c1.y, c2.y, 0.0f);
    dst[2] = make_float4(c0.z, c1.z, c2.z, 0.0f);
    dst[3] = make_float4(c0.w, c1.w, c2.w, 0.0f);
}

// ---------------------------------------------------------------------------
// Stage 1: comp_disp = flow_inv + STN(flow_fwd, flow_inv)
// STN: trilinear sample of flow_fwd at (grid + flow_inv), align_corners=True,
// zeros padding (masked through weights). Gathers are float4 (1 LDG.128 per
// corner instead of 3 LDG.32).
// ---------------------------------------------------------------------------
__global__ __launch_bounds__(128) void stage1_kernel(const float* __restrict__ finv) {
    const int x = blockIdx.x * 32 + threadIdx.x;
    const int y = blockIdx.y * 4 + threadIdx.y;
    const int bz = blockIdx.z;
    const int b = bz / Dd;
    const int z = bz - b * Dd;

    const int lin = (z * Hh + y) * Ww + x;
    const long bbase = (long)b * 3 * DHW;

    const float fz = __ldg(finv + bbase + lin);
    const float fy = __ldg(finv + bbase + DHW + lin);
    const float fx = __ldg(finv + bbase + 2 * DHW + lin);

    const float lz = (float)z + fz;
    const float ly = (float)y + fy;
    const float lx = (float)x + fx;

    // normalize then unnormalize, align_corners=True (reference op order)
    const float nx = 2.0f * (lx * (1.0f / (Ww - 1)) - 0.5f);
    const float ny = 2.0f * (ly * (1.0f / (Hh - 1)) - 0.5f);
    const float nz = 2.0f * (lz * (1.0f / (Dd - 1)) - 0.5f);
    const float ix = (nx + 1.0f) * 0.5f * (Ww - 1);
    const float iy = (ny + 1.0f) * 0.5f * (Hh - 1);
    const float iz = (nz + 1.0f) * 0.5f * (Dd - 1);

    const float x0f = floorf(ix), y0f = floorf(iy), z0f = floorf(iz);
    const float wx1 = ix - x0f, wy1 = iy - y0f, wz1 = iz - z0f;
    const int x0 = (int)x0f, y0 = (int)y0f, z0 = (int)z0f;
    const int x1 = x0 + 1, y1 = y0 + 1, z1 = z0 + 1;

    // zeros padding: mask invalid corners via weights, read from clipped index
    const float wx0 = (1.0f - wx1) * ((x0 >= 0 && x0 < Ww) ? 1.0f : 0.0f);
    const float wx1m = wx1 * ((x1 >= 0 && x1 < Ww) ? 1.0f : 0.0f);
    const float wy0 = (1.0f - wy1) * ((y0 >= 0 && y0 < Hh) ? 1.0f : 0.0f);
    const float wy1m = wy1 * ((y1 >= 0 && y1 < Hh) ? 1.0f : 0.0f);
    const float wz0 = (1.0f - wz1) * ((z0 >= 0 && z0 < Dd) ? 1.0f : 0.0f);
    const float wz1m = wz1 * ((z1 >= 0 && z1 < Dd) ? 1.0f : 0.0f);

    const int xc0 = min(max(x0, 0), Ww - 1), xc1 = min(max(x1, 0), Ww - 1);
    const int yc0 = min(max(y0, 0), Hh - 1), yc1 = min(max(y1, 0), Hh - 1);
    const int zc0 = min(max(z0, 0), Dd - 1), zc1 = min(max(z1, 0), Dd - 1);

    const float4* __restrict__ base4 = g_fwd4 + (long)b * DHW;
    const int r00 = (zc0 * Hh + yc0) * Ww;
    const int r01 = (zc0 * Hh + yc1) * Ww;
    const int r10 = (zc1 * Hh + yc0) * Ww;
    const int r11 = (zc1 * Hh + yc1) * Ww;

    // 8 independent LDG.128s, front-batched for MLP
    const float4 v000 = __ldg(base4 + r00 + xc0);
    const float4 v001 = __ldg(base4 + r00 + xc1);
    const float4 v010 = __ldg(base4 + r01 + xc0);
    const float4 v011 = __ldg(base4 + r01 + xc1);
    const float4 v100 = __ldg(base4 + r10 + xc0);
    const float4 v101 = __ldg(base4 + r10 + xc1);
    const float4 v110 = __ldg(base4 + r11 + xc0);
    const float4 v111 = __ldg(base4 + r11 + xc1);

    const float w000 = wz0 * wy0 * wx0;
    const float w001 = wz0 * wy0 * wx1m;
    const float w010 = wz0 * wy1m * wx0;
    const float w011 = wz0 * wy1m * wx1m;
    const float w100 = wz1m * wy0 * wx0;
    const float w101 = wz1m * wy0 * wx1m;
    const float w110 = wz1m * wy1m * wx0;
    const float w111 = wz1m * wy1m * wx1m;

    float a0, a1, a2;
    a0 = w000 * v000.x; a1 = w000 * v000.y; a2 = w000 * v000.z;
    a0 += w001 * v001.x; a1 += w001 * v001.y; a2 += w001 * v001.z;
    a0 += w010 * v010.x; a1 += w010 * v010.y; a2 += w010 * v010.z;
    a0 += w011 * v011.x; a1 += w011 * v011.y; a2 += w011 * v011.z;
    a0 += w100 * v100.x; a1 += w100 * v100.y; a2 += w100 * v100.z;
    a0 += w101 * v101.x; a1 += w101 * v101.y; a2 += w101 * v101.z;
    a0 += w110 * v110.x; a1 += w110 * v110.y; a2 += w110 * v110.z;
    a0 += w111 * v111.x; a1 += w111 * v111.y; a2 += w111 * v111.z;

    g_comp[b * DHW + lin] = make_float4(fz + a0, fy + a1, fx + a2, 0.0f);
}

// ---------------------------------------------------------------------------
// Stage 2: per-point penalty via 4 trilinear samples of comp_disp
// (align_corners=False, border padding). The 4 samples share the base corner
// cube; each axis-shifted sample either reuses it exactly (floor unchanged,
// ~83% of cases) or needs one extra 4-corner face at floor+2.
// ---------------------------------------------------------------------------
__device__ __forceinline__ float4 lerp4(float4 a, float4 b, float t) {
    return make_float4(a.x + (b.x - a.x) * t,
                       a.y + (b.y - a.y) * t,
                       a.z + (b.z - a.z) * t, 0.0f);
}

// c[z][y][x] corner order: c000,c001,c010,c011,c100,c101,c110,c111 (last=x)
__device__ __forceinline__ float3 trilerp(float4 c000, float4 c001, float4 c010, float4 c011,
                                          float4 c100, float4 c101, float4 c110, float4 c111,
                                          float wx, float wy, float wz) {
    const float4 a00 = lerp4(c000, c001, wx);
    const float4 a01 = lerp4(c010, c011, wx);
    const float4 a10 = lerp4(c100, c101, wx);
    const float4 a11 = lerp4(c110, c111, wx);
    const float4 b0 = lerp4(a00, a01, wy);
    const float4 b1 = lerp4(a10, a11, wy);
    const float4 c = lerp4(b0, b1, wz);
    return make_float3(c.x, c.y, c.z);
}

// align_corners=False unnormalized index, replicating reference op sequence
__device__ __forceinline__ float unnorm_nc(float s, int size, float inv_sm1) {
    const float n = 2.0f * (s * inv_sm1 - 0.5f);
    return ((n + 1.0f) * (float)size - 1.0f) * 0.5f;
}

__global__ __launch_bounds__(S2_BLOCK) void stage2_kernel(const int* __restrict__ idx) {
    const int n = blockIdx.x * S2_BLOCK + threadIdx.x;
    const int b = blockIdx.y;

    float pen = 0.0f;
    if (n < NSUB) {
        const int id = __ldg(idx + n);
        const int z = id / HW;
        const int rem = id - z * HW;
        const int y = rem / Ww;
        const int x = rem - y * Ww;
        const float px = (float)x, py = (float)y, pz = (float)z;

        // dxs = ([D,H,W]-1)*1e-3 applied to pts axes (x,y,z) in that order
        const float dx0 = (float)(Dd - 1) * 1e-3f;  // shifts x
        const float dx1 = (float)(Hh - 1) * 1e-3f;  // shifts y
        const float dx2 = (float)(Ww - 1) * 1e-3f;  // shifts z

        // shifted coords + realized deltas (fp32 rounding, matches reference)
        const float sxa = px + dx0, syb = py + dx1, szc = pz + dx2;
        const float dda = sxa - px, ddb = syb - py, ddc = szc - pz;

        const float4* __restrict__ base = g_comp + (long)b * DHW;

        // ---- base sample coords ----
        const float invW = 1.0f / (Ww - 1), invH = 1.0f / (Hh - 1), invD = 1.0f / (Dd - 1);
        const float ix = unnorm_nc(px, Ww, invW);
        const float iy = unnorm_nc(py, Hh, invH);
        const float iz = unnorm_nc(pz, Dd, invD);
        const float x0f = floorf(ix), y0f = floorf(iy), z0f = floorf(iz);
        const float wx = ix - x0f, wy = iy - y0f, wz = iz - z0f;
        const int x0 = (int)x0f, y0 = (int)y0f, z0 = (int)z0f;

        const int xc0 = min(max(x0, 0), Ww - 1), xc1 = min(max(x0 + 1, 0), Ww - 1);
        const int yc0 = min(max(y0, 0), Hh - 1), yc1 = min(max(y0 + 1, 0), Hh - 1);
        const int zc0 = min(max(z0, 0), Dd - 1), zc1 = min(max(z0 + 1, 0), Dd - 1);

        const int r00 = (zc0 * Hh + yc0) * Ww;
        const int r01 = (zc0 * Hh + yc1) * Ww;
        const int r10 = (zc1 * Hh + yc0) * Ww;
        const int r11 = (zc1 * Hh + yc1) * Ww;

        const float4 v000 = __ldg(base + r00 + xc0);
        const float4 v001 = __ldg(base + r00 + xc1);
        const float4 v010 = __ldg(base + r01 + xc0);
        const float4 v011 = __ldg(base + r01 + xc1);
        const float4 v100 = __ldg(base + r10 + xc0);
        const float4 v101 = __ldg(base + r10 + xc1);
        const float4 v110 = __ldg(base + r11 + xc0);
        const float4 v111 = __ldg(base + r11 + xc1);

        const float3 v0 = trilerp(v000, v001, v010, v011, v100, v101, v110, v111, wx, wy, wz);

        // ---- x-shifted sample ----
        float3 va;
        {
            const float ixa = unnorm_nc(sxa, Ww, invW);
            const float xaf = floorf(ixa);
            const float wxa = ixa - xaf;
            const int xa0 = (int)xaf;
            if (xa0 == x0) {
                va = trilerp(v000, v001, v010, v011, v100, v101, v110, v111, wxa, wy, wz);
            } else {  // crossed: low-x face = base high-x, high-x face at x0+2
                const int xc2 = min(max(x0 + 2, 0), Ww - 1);
                const float4 u00 = __ldg(base + r00 + xc2);
                const float4 u01 = __ldg(base + r01 + xc2);
                const float4 u10 = __ldg(base + r10 + xc2);
                const float4 u11 = __ldg(base + r11 + xc2);
                va = trilerp(v001, u00, v011, u01, v101, u10, v111, u11, wxa, wy, wz);
            }
        }

        // ---- y-shifted sample ----
        float3 vb;
        {
            const float iyb = unnorm_nc(syb, Hh, invH);
            const float ybf = floorf(iyb);
            const float wyb = iyb - ybf;
            const int yb0 = (int)ybf;
            if (yb0 == y0) {
                vb = trilerp(v000, v001, v010, v011, v100, v101, v110, v111, wx, wyb, wz);
            } else {  // crossed: low-y face = base high-y, high-y face at y0+2
                const int yc2 = min(max(y0 + 2, 0), Hh - 1);
                const int r02 = (zc0 * Hh + yc2) * Ww;
                const int r12 = (zc1 * Hh + yc2) * Ww;
                const float4 u00 = __ldg(base + r02 + xc0);
                const float4 u01 = __ldg(base + r02 + xc1);
                const float4 u10 = __ldg(base + r12 + xc0);
                const float4 u11 = __ldg(base + r12 + xc1);
                vb = trilerp(v010, v011, u00, u01, v110, v111, u10, u11, wx, wyb, wz);
            }
        }

        // ---- z-shifted sample ----
        float3 vc;
        {
            const float izc = unnorm_nc(szc, Dd, invD);
            const float zcf = floorf(izc);
            const float wzc = izc - zcf;
            const int zb0 = (int)zcf;
            if (zb0 == z0) {
                vc = trilerp(v000, v001, v010, v011, v100, v101, v110, v111, wx, wy, wzc);
            } else {  // crossed: low-z face = base high-z, high-z face at z0+2
                const int zc2 = min(max(z0 + 2, 0), Dd - 1);
                const int r20 = (zc2 * Hh + yc0) * Ww;
                const int r21 = (zc2 * Hh + yc1) * Ww;
                const float4 u00 = __ldg(base + r20 + xc0);
                const float4 u01 = __ldg(base + r20 + xc1);
                const float4 u10 = __ldg(base + r21 + xc0);
                const float4 u11 = __ldg(base + r21 + xc1);
                vc = trilerp(v100, v101, v110, v111, u00, u01, u10, u11, wx, wy, wzc);
            }
        }

        // J columns: col_a = ((shift - pts) + (v_shift - v0)) / dx_a; penalty = ||J - I||^2.
        // Off-diagonals: (shift - pts) component is exactly 0.
        // Diagonals: use realized fp32 delta dd* (matches reference rounding).
        const float ia = 1.0f / dx0, ib = 1.0f / dx1, ic = 1.0f / dx2;
        float t;
        t = (dda + (va.x - v0.x)) * ia - 1.0f; pen += t * t;  // J[0][0]-1
        t = (va.y - v0.y) * ia; pen += t * t;
        t = (va.z - v0.z) * ia; pen += t * t;
        t = (vb.x - v0.x) * ib; pen += t * t;
        t = (ddb + (vb.y - v0.y)) * ib - 1.0f; pen += t * t;  // J[1][1]-1
        t = (vb.z - v0.z) * ib; pen += t * t;
        t = (vc.x - v0.x) * ic; pen += t * t;
        t = (vc.y - v0.y) * ic; pen += t * t;
        t = (ddc + (vc.z - v0.z)) * ic - 1.0f; pen += t * t;  // J[2][2]-1
    }

    // deterministic block reduction -> per-block partial sum (no atomics)
    #pragma unroll
    for (int off = 16; off > 0; off >>= 1)
        pen += __shfl_down_sync(0xFFFFFFFFu, pen, off);

    __shared__ float warp_sums[S2_BLOCK / 32];
    const int lane = threadIdx.x & 31;
    const int wid = threadIdx.x >> 5;
    if (lane == 0) warp_sums[wid] = pen;
    __syncthreads();
    if (wid == 0) {
        float s = (lane < S2_BLOCK / 32) ? warp_sums[lane] : 0.0f;
        #pragma unroll
        for (int off = 4; off > 0; off >>= 1)
            s += __shfl_down_sync(0xFFFFFFFFu, s, off);
        if (lane == 0)
            g_partial[blockIdx.y * S2_BLOCKS_PER_B + blockIdx.x] = s;
    }
}

// Fixed-order tree reduction of the partial sums: bitwise deterministic.
__global__ __launch_bounds__(256) void finalize_kernel(float* __restrict__ out) {
    __shared__ double sh[256];
    double acc = 0.0;
    for (int i = threadIdx.x; i < S2_TOTAL_BLOCKS; i += 256)
        acc += (double)g_partial[i];
    sh[threadIdx.x] = acc;
    __syncthreads();
    #pragma unroll
    for (int off = 128; off > 0; off >>= 1) {
        if (threadIdx.x < off) sh[threadIdx.x] += sh[threadIdx.x + off];
        __syncthreads();
    }
    if (threadIdx.x == 0)
        out[0] = (float)(sh[0] / (double)((long)NB * NSUB));
}

extern "C" void kernel_launch(void* const* d_in, const int* in_sizes, int n_in,
                              void* d_out, int out_size) {
    const float* ffwd = (const float*)d_in[0];
    const float* finv = (const float*)d_in[1];
    const int* idx = (const int*)d_in[2];
    float* out = (float*)d_out;

    interleave_kernel<<<(NB * DHW / 4) / 256, 256>>>(ffwd);

    dim3 blk1(32, 4, 1);
    dim3 grd1(Ww / 32, Hh / 4, NB * Dd);
    stage1_kernel<<<grd1, blk1>>>(finv);

    dim3 grd2(S2_BLOCKS_PER_B, NB, 1);
    stage2_kernel<<<grd2, S2_BLOCK>>>(idx);

    finalize_kernel<<<1, 256>>>(out);
}

// round 11
// speedup vs baseline: 1.0737x; 1.0737x over previous
#include <cuda_runtime.h>

#define Dd 160
#define Hh 192
#define Ww 160
#define HW (Hh * Ww)
#define DHW (Dd * Hh * Ww)
#define NSUB (DHW / 8)
#define NB 2
#define S2_BLOCK 256
#define S2_BLOCKS_PER_B (NSUB / S2_BLOCK)       // 2400
#define S2_TOTAL_BLOCKS (NB * S2_BLOCKS_PER_B)  // 4800

// Composed displacement field, channel-interleaved: (c0,c1,c2,pad) per voxel.
__device__ float4 g_comp[NB * DHW];
__device__ float g_partial[S2_TOTAL_BLOCKS];

// ---------------------------------------------------------------------------
// Stage 1: comp_disp = flow_inv + STN(flow_fwd, flow_inv)
// STN: trilinear sample of flow_fwd at (grid + flow_inv), align_corners=True,
// zeros padding (masked through weights). Planar gathers (proven 189.6us
// config; interleaved-LDG.128 variant measured neutral + pre-pass cost).
// ---------------------------------------------------------------------------
__global__ __launch_bounds__(128) void stage1_kernel(const float* __restrict__ ffwd,
                                                     const float* __restrict__ finv) {
    const int x = blockIdx.x * 32 + threadIdx.x;
    const int y = blockIdx.y * 4 + threadIdx.y;
    const int bz = blockIdx.z;
    const int b = bz / Dd;
    const int z = bz - b * Dd;

    const int lin = (z * Hh + y) * Ww + x;
    const long bbase = (long)b * 3 * DHW;

    const float fz = finv[bbase + lin];
    const float fy = finv[bbase + DHW + lin];
    const float fx = finv[bbase + 2 * DHW + lin];

    const float lz = (float)z + fz;
    const float ly = (float)y + fy;
    const float lx = (float)x + fx;

    // normalize then unnormalize, align_corners=True (reference op order)
    const float nx = 2.0f * (lx * (1.0f / (Ww - 1)) - 0.5f);
    const float ny = 2.0f * (ly * (1.0f / (Hh - 1)) - 0.5f);
    const float nz = 2.0f * (lz * (1.0f / (Dd - 1)) - 0.5f);
    const float ix = (nx + 1.0f) * 0.5f * (Ww - 1);
    const float iy = (ny + 1.0f) * 0.5f * (Hh - 1);
    const float iz = (nz + 1.0f) * 0.5f * (Dd - 1);

    const float x0f = floorf(ix), y0f = floorf(iy), z0f = floorf(iz);
    const float wx1 = ix - x0f, wy1 = iy - y0f, wz1 = iz - z0f;
    const int x0 = (int)x0f, y0 = (int)y0f, z0 = (int)z0f;
    const int x1 = x0 + 1, y1 = y0 + 1, z1 = z0 + 1;

    // zeros padding: mask invalid corners, read from clipped index
    const float wx0 = (1.0f - wx1) * ((x0 >= 0 && x0 < Ww) ? 1.0f : 0.0f);
    const float wx1m = wx1 * ((x1 >= 0 && x1 < Ww) ? 1.0f : 0.0f);
    const float wy0 = (1.0f - wy1) * ((y0 >= 0 && y0 < Hh) ? 1.0f : 0.0f);
    const float wy1m = wy1 * ((y1 >= 0 && y1 < Hh) ? 1.0f : 0.0f);
    const float wz0 = (1.0f - wz1) * ((z0 >= 0 && z0 < Dd) ? 1.0f : 0.0f);
    const float wz1m = wz1 * ((z1 >= 0 && z1 < Dd) ? 1.0f : 0.0f);

    const int xc0 = min(max(x0, 0), Ww - 1), xc1 = min(max(x1, 0), Ww - 1);
    const int yc0 = min(max(y0, 0), Hh - 1), yc1 = min(max(y1, 0), Hh - 1);
    const int zc0 = min(max(z0, 0), Dd - 1), zc1 = min(max(z1, 0), Dd - 1);

    const float* __restrict__ base = ffwd + bbase;
    const int r00 = (zc0 * Hh + yc0) * Ww;
    const int r01 = (zc0 * Hh + yc1) * Ww;
    const int r10 = (zc1 * Hh + yc0) * Ww;
    const int r11 = (zc1 * Hh + yc1) * Ww;

    float a0 = 0.0f, a1 = 0.0f, a2 = 0.0f;
#define TAP(off, w)                                           \
    do {                                                      \
        const float _w = (w);                                 \
        if (_w != 0.0f) {                                     \
            const int _o = (off);                             \
            a0 += _w * __ldg(base + _o);                      \
            a1 += _w * __ldg(base + _o + DHW);                \
            a2 += _w * __ldg(base + _o + 2 * DHW);            \
        }                                                     \
    } while (0)

    TAP(r00 + xc0, wz0 * wy0 * wx0);
    TAP(r00 + xc1, wz0 * wy0 * wx1m);
    TAP(r01 + xc0, wz0 * wy1m * wx0);
    TAP(r01 + xc1, wz0 * wy1m * wx1m);
    TAP(r10 + xc0, wz1m * wy0 * wx0);
    TAP(r10 + xc1, wz1m * wy0 * wx1m);
    TAP(r11 + xc0, wz1m * wy1m * wx0);
    TAP(r11 + xc1, wz1m * wy1m * wx1m);
#undef TAP

    g_comp[b * DHW + lin] = make_float4(fz + a0, fy + a1, fx + a2, 0.0f);
}

// ---------------------------------------------------------------------------
// Stage 2: per-point penalty via 4 trilinear samples of comp_disp
// (align_corners=False, border padding). The 4 samples share the base corner
// cube; each axis-shifted sample either reuses it exactly (floor unchanged,
// ~83% of cases) or needs one extra 4-corner face at floor+2.
// ---------------------------------------------------------------------------
__device__ __forceinline__ float4 lerp4(float4 a, float4 b, float t) {
    return make_float4(a.x + (b.x - a.x) * t,
                       a.y + (b.y - a.y) * t,
                       a.z + (b.z - a.z) * t, 0.0f);
}

// c[z][y][x] corner order: c000,c001,c010,c011,c100,c101,c110,c111 (last=x)
__device__ __forceinline__ float3 trilerp(float4 c000, float4 c001, float4 c010, float4 c011,
                                          float4 c100, float4 c101, float4 c110, float4 c111,
                                          float wx, float wy, float wz) {
    const float4 a00 = lerp4(c000, c001, wx);
    const float4 a01 = lerp4(c010, c011, wx);
    const float4 a10 = lerp4(c100, c101, wx);
    const float4 a11 = lerp4(c110, c111, wx);
    const float4 b0 = lerp4(a00, a01, wy);
    const float4 b1 = lerp4(a10, a11, wy);
    const float4 c = lerp4(b0, b1, wz);
    return make_float3(c.x, c.y, c.z);
}

// align_corners=False unnormalized index, replicating reference op sequence
__device__ __forceinline__ float unnorm_nc(float s, int size, float inv_sm1) {
    const float n = 2.0f * (s * inv_sm1 - 0.5f);
    return ((n + 1.0f) * (float)size - 1.0f) * 0.5f;
}

__global__ __launch_bounds__(S2_BLOCK) void stage2_kernel(const int* __restrict__ idx) {
    const int n = blockIdx.x * S2_BLOCK + threadIdx.x;
    const int b = blockIdx.y;

    float pen = 0.0f;
    if (n < NSUB) {
        const int id = __ldg(idx + n);
        const int z = id / HW;
        const int rem = id - z * HW;
        const int y = rem / Ww;
        const int x = rem - y * Ww;
        const float px = (float)x, py = (float)y, pz = (float)z;

        // dxs = ([D,H,W]-1)*1e-3 applied to pts axes (x,y,z) in that order
        const float dx0 = (float)(Dd - 1) * 1e-3f;  // shifts x
        const float dx1 = (float)(Hh - 1) * 1e-3f;  // shifts y
        const float dx2 = (float)(Ww - 1) * 1e-3f;  // shifts z

        // shifted coords + realized deltas (fp32 rounding, matches reference)
        const float sxa = px + dx0, syb = py + dx1, szc = pz + dx2;
        const float dda = sxa - px, ddb = syb - py, ddc = szc - pz;

        const float4* __restrict__ base = g_comp + (long)b * DHW;

        // ---- base sample coords ----
        const float invW = 1.0f / (Ww - 1), invH = 1.0f / (Hh - 1), invD = 1.0f / (Dd - 1);
        const float ix = unnorm_nc(px, Ww, invW);
        const float iy = unnorm_nc(py, Hh, invH);
        const float iz = unnorm_nc(pz, Dd, invD);
        const float x0f = floorf(ix), y0f = floorf(iy), z0f = floorf(iz);
        const float wx = ix - x0f, wy = iy - y0f, wz = iz - z0f;
        const int x0 = (int)x0f, y0 = (int)y0f, z0 = (int)z0f;

        const int xc0 = min(max(x0, 0), Ww - 1), xc1 = min(max(x0 + 1, 0), Ww - 1);
        const int yc0 = min(max(y0, 0), Hh - 1), yc1 = min(max(y0 + 1, 0), Hh - 1);
        const int zc0 = min(max(z0, 0), Dd - 1), zc1 = min(max(z0 + 1, 0), Dd - 1);

        const int r00 = (zc0 * Hh + yc0) * Ww;
        const int r01 = (zc0 * Hh + yc1) * Ww;
        const int r10 = (zc1 * Hh + yc0) * Ww;
        const int r11 = (zc1 * Hh + yc1) * Ww;

        const float4 v000 = __ldg(base + r00 + xc0);
        const float4 v001 = __ldg(base + r00 + xc1);
        const float4 v010 = __ldg(base + r01 + xc0);
        const float4 v011 = __ldg(base + r01 + xc1);
        const float4 v100 = __ldg(base + r10 + xc0);
        const float4 v101 = __ldg(base + r10 + xc1);
        const float4 v110 = __ldg(base + r11 + xc0);
        const float4 v111 = __ldg(base + r11 + xc1);

        const float3 v0 = trilerp(v000, v001, v010, v011, v100, v101, v110, v111, wx, wy, wz);

        // ---- x-shifted sample ----
        float3 va;
        {
            const float ixa = unnorm_nc(sxa, Ww, invW);
            const float xaf = floorf(ixa);
            const float wxa = ixa - xaf;
            const int xa0 = (int)xaf;
            if (xa0 == x0) {
                va = trilerp(v000, v001, v010, v011, v100, v101, v110, v111, wxa, wy, wz);
            } else {  // crossed: low-x face = base high-x, high-x face at x0+2
                const int xc2 = min(max(x0 + 2, 0), Ww - 1);
                const float4 u00 = __ldg(base + r00 + xc2);
                const float4 u01 = __ldg(base + r01 + xc2);
                const float4 u10 = __ldg(base + r10 + xc2);
                const float4 u11 = __ldg(base + r11 + xc2);
                va = trilerp(v001, u00, v011, u01, v101, u10, v111, u11, wxa, wy, wz);
            }
        }

        // ---- y-shifted sample ----
        float3 vb;
        {
            const float iyb = unnorm_nc(syb, Hh, invH);
            const float ybf = floorf(iyb);
            const float wyb = iyb - ybf;
            const int yb0 = (int)ybf;
            if (yb0 == y0) {
                vb = trilerp(v000, v001, v010, v011, v100, v101, v110, v111, wx, wyb, wz);
            } else {  // crossed: low-y face = base high-y, high-y face at y0+2
                const int yc2 = min(max(y0 + 2, 0), Hh - 1);
                const int r02 = (zc0 * Hh + yc2) * Ww;
                const int r12 = (zc1 * Hh + yc2) * Ww;
                const float4 u00 = __ldg(base + r02 + xc0);
                const float4 u01 = __ldg(base + r02 + xc1);
                const float4 u10 = __ldg(base + r12 + xc0);
                const float4 u11 = __ldg(base + r12 + xc1);
                vb = trilerp(v010, v011, u00, u01, v110, v111, u10, u11, wx, wyb, wz);
            }
        }

        // ---- z-shifted sample ----
        float3 vc;
        {
            const float izc = unnorm_nc(szc, Dd, invD);
            const float zcf = floorf(izc);
            const float wzc = izc - zcf;
            const int zb0 = (int)zcf;
            if (zb0 == z0) {
                vc = trilerp(v000, v001, v010, v011, v100, v101, v110, v111, wx, wy, wzc);
            } else {  // crossed: low-z face = base high-z, high-z face at z0+2
                const int zc2 = min(max(z0 + 2, 0), Dd - 1);
                const int r20 = (zc2 * Hh + yc0) * Ww;
                const int r21 = (zc2 * Hh + yc1) * Ww;
                const float4 u00 = __ldg(base + r20 + xc0);
                const float4 u01 = __ldg(base + r20 + xc1);
                const float4 u10 = __ldg(base + r21 + xc0);
                const float4 u11 = __ldg(base + r21 + xc1);
                vc = trilerp(v100, v101, v110, v111, u00, u01, u10, u11, wx, wy, wzc);
            }
        }

        // J columns: col_a = ((shift - pts) + (v_shift - v0)) / dx_a; penalty = ||J - I||^2.
        // Off-diagonals: (shift - pts) component is exactly 0.
        // Diagonals: use realized fp32 delta dd* (matches reference rounding).
        const float ia = 1.0f / dx0, ib = 1.0f / dx1, ic = 1.0f / dx2;
        float t;
        t = (dda + (va.x - v0.x)) * ia - 1.0f; pen += t * t;  // J[0][0]-1
        t = (va.y - v0.y) * ia; pen += t * t;
        t = (va.z - v0.z) * ia; pen += t * t;
        t = (vb.x - v0.x) * ib; pen += t * t;
        t = (ddb + (vb.y - v0.y)) * ib - 1.0f; pen += t * t;  // J[1][1]-1
        t = (vb.z - v0.z) * ib; pen += t * t;
        t = (vc.x - v0.x) * ic; pen += t * t;
        t = (vc.y - v0.y) * ic; pen += t * t;
        t = (ddc + (vc.z - v0.z)) * ic - 1.0f; pen += t * t;  // J[2][2]-1
    }

    // deterministic block reduction -> per-block partial sum (no atomics)
    #pragma unroll
    for (int off = 16; off > 0; off >>= 1)
        pen += __shfl_down_sync(0xFFFFFFFFu, pen, off);

    __shared__ float warp_sums[S2_BLOCK / 32];
    const int lane = threadIdx.x & 31;
    const int wid = threadIdx.x >> 5;
    if (lane == 0) warp_sums[wid] = pen;
    __syncthreads();
    if (wid == 0) {
        float s = (lane < S2_BLOCK / 32) ? warp_sums[lane] : 0.0f;
        #pragma unroll
        for (int off = 4; off > 0; off >>= 1)
            s += __shfl_down_sync(0xFFFFFFFFu, s, off);
        if (lane == 0)
            g_partial[blockIdx.y * S2_BLOCKS_PER_B + blockIdx.x] = s;
    }
}

// Fixed-order tree reduction of the partial sums: bitwise deterministic.
// float4 reads: 1200 vector loads instead of 4800 scalar (profiled 14.7us ->
// expect ~5us; single block was serialized on scalar load latency).
__global__ __launch_bounds__(256) void finalize_kernel(float* __restrict__ out) {
    __shared__ double sh[256];
    const float4* __restrict__ p4 = (const float4*)g_partial;
    double acc = 0.0;
    for (int i = threadIdx.x; i < S2_TOTAL_BLOCKS / 4; i += 256) {
        const float4 v = p4[i];
        acc += (double)v.x + (double)v.y + (double)v.z + (double)v.w;
    }
    sh[threadIdx.x] = acc;
    __syncthreads();
    #pragma unroll
    for (int off = 128; off > 0; off >>= 1) {
        if (threadIdx.x < off) sh[threadIdx.x] += sh[threadIdx.x + off];
        __syncthreads();
    }
    if (threadIdx.x == 0)
        out[0] = (float)(sh[0] / (double)((long)NB * NSUB));
}

extern "C" void kernel_launch(void* const* d_in, const int* in_sizes, int n_in,
                              void* d_out, int out_size) {
    const float* ffwd = (const float*)d_in[0];
    const float* finv = (const float*)d_in[1];
    const int* idx = (const int*)d_in[2];
    float* out = (float*)d_out;

    dim3 blk1(32, 4, 1);
    dim3 grd1(Ww / 32, Hh / 4, NB * Dd);
    stage1_kernel<<<grd1, blk1>>>(ffwd, finv);

    dim3 grd2(S2_BLOCKS_PER_B, NB, 1);
    stage2_kernel<<<grd2, S2_BLOCK>>>(idx);

    finalize_kernel<<<1, 256>>>(out);
}